// round 12
// baseline (speedup 1.0000x reference)
#include <cuda_runtime.h>
#include <cuda_bf16.h>
#include <cstdint>
#include <math.h>

#define HW 4096
#define Tn 50

typedef uint32_t u32;
typedef unsigned short u16;

// Scratch (static __device__ arrays — allocation-free per harness rules)
__device__ float g_XC[400u * 128u * 4096u];   // [t*8+b][128][4096]
__device__ float g_Y[8 * 32 * 4096];
__device__ float g_Z[8 * 32 * 4096];
__device__ float g_G2[8 * 32 * 4096];

#define KPAD   296            // u16 elements per weight row (288 used)
#define KPAD32 (KPAD / 2)     // 148 u32 per row
// Packed bf16 hi/lo weights: rows 0..127 = Wx, 128..223 = Wy, 224..255 = Wz
__device__ u16 g_WH[256 * KPAD];
__device__ u16 g_WL[256 * KPAD];

__device__ __forceinline__ float fsigmoid(float x) {
    return 1.0f / (1.0f + __expf(-x));
}
__device__ __forceinline__ float ftanh(float x) {
    x = fminf(fmaxf(x, -12.0f), 12.0f);
    float e = __expf(2.0f * x);
    return 1.0f - 2.0f / (e + 1.0f);
}

// mma.sync m16n8k16 bf16 (baseline PTX, sm_80+; tensor pipe)
__device__ __forceinline__ void mma16816(float* d,
                                         u32 a0, u32 a1, u32 a2, u32 a3,
                                         u32 b0, u32 b1) {
    asm volatile(
        "mma.sync.aligned.m16n8k16.row.col.f32.bf16.bf16.f32 "
        "{%0,%1,%2,%3}, {%4,%5,%6,%7}, {%8,%9}, {%0,%1,%2,%3};"
        : "+f"(d[0]), "+f"(d[1]), "+f"(d[2]), "+f"(d[3])
        : "r"(a0), "r"(a1), "r"(a2), "r"(a3), "r"(b0), "r"(b1));
}

// ---------------------------------------------------------------------------
// One-time weight prep: float -> bf16 hi/lo, layout [row][k], k = tap*32 + ci
// ---------------------------------------------------------------------------
__global__ void prep_w(const float* __restrict__ Wx,
                       const float* __restrict__ Wy,
                       const float* __restrict__ Wz)
{
    int idx = blockIdx.x * 256 + threadIdx.x;
    if (idx >= 256 * KPAD) return;
    int row = idx / KPAD, k = idx - row * KPAD;
    u16 h = 0, l = 0;
    if (k < 288) {
        int tap = k >> 5, ci = k & 31;
        const float* W; int co;
        if (row < 128)      { W = Wx; co = row; }
        else if (row < 224) { W = Wy; co = row - 128; }
        else                { W = Wz; co = row - 224; }
        float w = W[((size_t)co * 32 + ci) * 9 + tap];
        __nv_bfloat16 wh = __float2bfloat16(w);
        __nv_bfloat16 wl = __float2bfloat16(w - __bfloat162float(wh));
        h = __bfloat16_as_ushort(wh);
        l = __bfloat16_as_ushort(wl);
    }
    g_WH[idx] = h;
    g_WL[idx] = l;
}

// ---------------------------------------------------------------------------
// Shared-memory layout for conv_tc (32 co per CTA) — unchanged from R11
// ---------------------------------------------------------------------------
#define CIPAD   40
#define AELEMS  (6 * 66 * CIPAD)                 // 15840
#define OFF_AH  0
#define OFF_AL  (AELEMS * 2)                     // 31680
#define OFF_WH  (OFF_AL + AELEMS * 2)            // 63360
#define OFF_WL  (OFF_WH + 32 * KPAD * 2)         // +18944
#define OFF_BI  (OFF_WL + 32 * KPAD * 2)
#define SMEM_SZ (OFF_BI + 128)

// ---------------------------------------------------------------------------
// conv_tc: 3x3 SAME conv, Cin=32, 32 co per CTA (used for MODE0 and MODE2).
// MODE 0: X -> g_XC (grid = 16 x 4 x 400)
// MODE 2: g_Z -> fused Y update -> g_Y and out (grid = 16 x 1 x 8)
// ---------------------------------------------------------------------------
template<int MODE>
__global__ void __launch_bounds__(256, 2)
conv_tc(const float* __restrict__ X,
        const u16* __restrict__ gWh,   // pre-sliced for this conv
        const u16* __restrict__ gWl,
        const float* __restrict__ bias,
        float* __restrict__ out,
        int t)
{
    extern __shared__ char smem[];
    u16*   sAh   = (u16*)(smem + OFF_AH);
    u16*   sAl   = (u16*)(smem + OFF_AL);
    u16*   sWh   = (u16*)(smem + OFF_WH);
    u16*   sWl   = (u16*)(smem + OFF_WL);
    float* sBias = (float*)(smem + OFF_BI);

    const int tid   = threadIdx.x;
    const int ytile = blockIdx.x;        // 4 image rows each
    const int cog   = blockIdx.y;
    const int img   = blockIdx.z;

    int b, ti;
    if (MODE == 0) { b = img & 7; ti = img >> 3; }
    else           { b = img;     ti = t; }

    const float* src;
    size_t in_base; int chstride;
    if (MODE == 0) { src = X;   in_base = ((size_t)b * 32 * Tn + ti) * HW; chstride = Tn * HW; }
    else           { src = g_Z; in_base = (size_t)b * 32 * HW; chstride = HW; }

    const int y0 = ytile * 4;

    // ---- stage weights: straight u32 copy from prepped arrays ----
    {
        const u32* wh32 = (const u32*)gWh + (size_t)cog * 32 * KPAD32;
        const u32* wl32 = (const u32*)gWl + (size_t)cog * 32 * KPAD32;
        for (int e = tid; e < 32 * KPAD32; e += 256) {
            ((u32*)sWh)[e] = wh32[e];
            ((u32*)sWl)[e] = wl32[e];
        }
    }
    if (tid < 32) sBias[tid] = bias[cog * 32 + tid];

    // ---- stage halo tile [6][66][ci] channel-major, SAME zero-padding ----
    for (int e = tid; e < 32 * 6 * 66; e += 256) {
        int ci = e / 396, r = e - ci * 396;
        int hy = r / 66,  hx = r - hy * 66;
        int gy = y0 - 1 + hy, gx = hx - 1;
        float v = 0.0f;
        if ((unsigned)gy < 64u && (unsigned)gx < 64u)
            v = src[in_base + (size_t)ci * chstride + gy * 64 + gx];
        __nv_bfloat16 h = __float2bfloat16(v);
        __nv_bfloat16 l = __float2bfloat16(v - __bfloat162float(h));
        int slot = (hy * 66 + hx) * CIPAD + ci;
        sAh[slot] = __bfloat16_as_ushort(h);
        sAl[slot] = __bfloat16_as_ushort(l);
    }
    __syncthreads();

    // ---- warp GEMM: M=32, N=32 ----
    const int wid  = tid >> 5;
    const int lane = tid & 31;
    const int gid  = lane >> 2;
    const int tig  = lane & 3;
    const int m0   = wid * 32;

    int abase[4];
#pragma unroll
    for (int r = 0; r < 4; r++) {
        int m  = m0 + r * 8 + gid;
        int py = m >> 6, px = m & 63;
        abase[r] = (py * 66 + px) * CIPAD + tig * 2;
    }
    int bbase[4];
#pragma unroll
    for (int nf = 0; nf < 4; nf++)
        bbase[nf] = (nf * 8 + gid) * KPAD + tig * 2;

    float acc[2][4][4];
#pragma unroll
    for (int mf = 0; mf < 2; mf++)
#pragma unroll
        for (int nf = 0; nf < 4; nf++)
#pragma unroll
            for (int i = 0; i < 4; i++) acc[mf][nf][i] = 0.0f;

#pragma unroll 1
    for (int tap = 0; tap < 9; tap++) {
        const int dy = tap / 3, dx = tap - dy * 3;
        const int aofs_t = (dy * 66 + dx) * CIPAD;
        const int bofs_t = tap * 32;
#pragma unroll
        for (int kc = 0; kc < 2; kc++) {
            const int aofs = aofs_t + kc * 16;
            const int bofs = bofs_t + kc * 16;

            u32 Ah[2][4], Al[2][4];
#pragma unroll
            for (int mf = 0; mf < 2; mf++) {
                int i0 = abase[2 * mf]     + aofs;
                int i1 = abase[2 * mf + 1] + aofs;
                Ah[mf][0] = *(const u32*)&sAh[i0];
                Ah[mf][1] = *(const u32*)&sAh[i1];
                Ah[mf][2] = *(const u32*)&sAh[i0 + 8];
                Ah[mf][3] = *(const u32*)&sAh[i1 + 8];
                Al[mf][0] = *(const u32*)&sAl[i0];
                Al[mf][1] = *(const u32*)&sAl[i1];
                Al[mf][2] = *(const u32*)&sAl[i0 + 8];
                Al[mf][3] = *(const u32*)&sAl[i1 + 8];
            }
#pragma unroll
            for (int nf = 0; nf < 4; nf++) {
                int j = bbase[nf] + bofs;
                u32 Bh0 = *(const u32*)&sWh[j];
                u32 Bh1 = *(const u32*)&sWh[j + 8];
                u32 Bl0 = *(const u32*)&sWl[j];
                u32 Bl1 = *(const u32*)&sWl[j + 8];
#pragma unroll
                for (int mf = 0; mf < 2; mf++) {
                    mma16816(acc[mf][nf], Ah[mf][0], Ah[mf][1], Ah[mf][2], Ah[mf][3], Bh0, Bh1);
                    mma16816(acc[mf][nf], Al[mf][0], Al[mf][1], Al[mf][2], Al[mf][3], Bh0, Bh1);
                    mma16816(acc[mf][nf], Ah[mf][0], Ah[mf][1], Ah[mf][2], Ah[mf][3], Bl0, Bl1);
                }
            }
        }
    }

    // ---- epilogue ----
#pragma unroll
    for (int mf = 0; mf < 2; mf++) {
#pragma unroll
        for (int nf = 0; nf < 4; nf++) {
#pragma unroll
            for (int i = 0; i < 4; i++) {
                int m   = m0 + mf * 16 + gid + (i >> 1) * 8;
                int n   = nf * 8 + tig * 2 + (i & 1);
                int pix = ytile * 256 + m;
                int co  = cog * 32 + n;
                float v = acc[mf][nf][i] + sBias[n];
                if (MODE == 0) {
                    g_XC[((size_t)img * 128 + co) * HW + pix] = v;
                } else {
                    size_t off = ((size_t)b * 32 + co) * HW + pix;
                    float g2 = g_G2[off];
                    float xy = g_XC[(((size_t)(t * 8 + b)) * 128 + 96 + co) * HW + pix];
                    float yv = g_Y[off];
                    float yn = fmaf(g2, ftanh(xy + v) - yv, yv);
                    g_Y[off] = yn;
                    out[((size_t)(b * 32 + co) * Tn + t) * HW + pix] = yn;
                }
            }
        }
    }
}

// ---------------------------------------------------------------------------
// Fused conv(Y, Wy) + gates + Z update.
// 256 thr = 8 warps; warp w owns M rows [w*32, w*32+32) and ALL 96 channels
// (nj = 0:yg1, 1:yg2, 2:yz). Each thread's acc triplet across nj shares the
// same (pixel, channel) -> Z/G2 update fully thread-local. No g_yconv.
// grid = (16 ytiles, 8 batch)
// ---------------------------------------------------------------------------
#define YOFF_WH  (AELEMS * 4)                    // after sAh+sAl (63360)
#define YOFF_WL  (YOFF_WH + 96 * KPAD * 2)       // +56832
#define YOFF_BI  (YOFF_WL + 96 * KPAD * 2)
#define YSMEM_SZ (YOFF_BI + 512)                 // ~177.5 KB

__global__ void __launch_bounds__(256, 1)
convY_k(const float* __restrict__ by, int t)
{
    extern __shared__ char smem[];
    u16*   sAh   = (u16*)(smem);
    u16*   sAl   = (u16*)(smem + AELEMS * 2);
    u16*   sWh   = (u16*)(smem + YOFF_WH);
    u16*   sWl   = (u16*)(smem + YOFF_WL);
    float* sBias = (float*)(smem + YOFF_BI);

    const int tid   = threadIdx.x;
    const int ytile = blockIdx.x;
    const int b     = blockIdx.y;
    const int y0    = ytile * 4;

    // ---- stage weights (Wy rows = 128..223 of prepped arrays) ----
    {
        const u32* wh32 = (const u32*)g_WH + (size_t)128 * KPAD32;
        const u32* wl32 = (const u32*)g_WL + (size_t)128 * KPAD32;
        for (int e = tid; e < 96 * KPAD32; e += 256) {
            ((u32*)sWh)[e] = wh32[e];
            ((u32*)sWl)[e] = wl32[e];
        }
    }
    if (tid < 96) sBias[tid] = by[tid];

    // ---- stage halo from g_Y ----
    const size_t in_base = (size_t)b * 32 * HW;
    for (int e = tid; e < 32 * 6 * 66; e += 256) {
        int ci = e / 396, r = e - ci * 396;
        int hy = r / 66,  hx = r - hy * 66;
        int gy = y0 - 1 + hy, gx = hx - 1;
        float v = 0.0f;
        if ((unsigned)gy < 64u && (unsigned)gx < 64u)
            v = g_Y[in_base + (size_t)ci * HW + gy * 64 + gx];
        __nv_bfloat16 h = __float2bfloat16(v);
        __nv_bfloat16 l = __float2bfloat16(v - __bfloat162float(h));
        int slot = (hy * 66 + hx) * CIPAD + ci;
        sAh[slot] = __bfloat16_as_ushort(h);
        sAl[slot] = __bfloat16_as_ushort(l);
    }
    __syncthreads();

    const int wid  = tid >> 5;
    const int lane = tid & 31;
    const int gid  = lane >> 2;
    const int tig  = lane & 3;
    const int m0   = wid * 32;

    int abase[4];
#pragma unroll
    for (int r = 0; r < 4; r++) {
        int m  = m0 + r * 8 + gid;
        int py = m >> 6, px = m & 63;
        abase[r] = (py * 66 + px) * CIPAD + tig * 2;
    }

    float acc[3][2][4][4];
#pragma unroll
    for (int nj = 0; nj < 3; nj++)
#pragma unroll
        for (int mf = 0; mf < 2; mf++)
#pragma unroll
            for (int nf = 0; nf < 4; nf++)
#pragma unroll
                for (int i = 0; i < 4; i++) acc[nj][mf][nf][i] = 0.0f;

#pragma unroll 1
    for (int tap = 0; tap < 9; tap++) {
        const int dy = tap / 3, dx = tap - dy * 3;
        const int aofs_t = (dy * 66 + dx) * CIPAD;
        const int bofs_t = tap * 32;
#pragma unroll
        for (int kc = 0; kc < 2; kc++) {
            const int aofs = aofs_t + kc * 16;
            const int bofs = bofs_t + kc * 16;

            u32 Ah[2][4], Al[2][4];
#pragma unroll
            for (int mf = 0; mf < 2; mf++) {
                int i0 = abase[2 * mf]     + aofs;
                int i1 = abase[2 * mf + 1] + aofs;
                Ah[mf][0] = *(const u32*)&sAh[i0];
                Ah[mf][1] = *(const u32*)&sAh[i1];
                Ah[mf][2] = *(const u32*)&sAh[i0 + 8];
                Ah[mf][3] = *(const u32*)&sAh[i1 + 8];
                Al[mf][0] = *(const u32*)&sAl[i0];
                Al[mf][1] = *(const u32*)&sAl[i1];
                Al[mf][2] = *(const u32*)&sAl[i0 + 8];
                Al[mf][3] = *(const u32*)&sAl[i1 + 8];
            }
#pragma unroll
            for (int nj = 0; nj < 3; nj++) {
#pragma unroll
                for (int nf = 0; nf < 4; nf++) {
                    int j = (nj * 32 + nf * 8 + gid) * KPAD + tig * 2 + bofs;
                    u32 Bh0 = *(const u32*)&sWh[j];
                    u32 Bh1 = *(const u32*)&sWh[j + 8];
                    u32 Bl0 = *(const u32*)&sWl[j];
                    u32 Bl1 = *(const u32*)&sWl[j + 8];
#pragma unroll
                    for (int mf = 0; mf < 2; mf++) {
                        mma16816(acc[nj][mf][nf], Ah[mf][0], Ah[mf][1], Ah[mf][2], Ah[mf][3], Bh0, Bh1);
                        mma16816(acc[nj][mf][nf], Al[mf][0], Al[mf][1], Al[mf][2], Al[mf][3], Bh0, Bh1);
                        mma16816(acc[nj][mf][nf], Ah[mf][0], Ah[mf][1], Ah[mf][2], Ah[mf][3], Bl0, Bl1);
                    }
                }
            }
        }
    }

    // ---- fused gate/Z epilogue: all data thread-local ----
#pragma unroll
    for (int mf = 0; mf < 2; mf++) {
#pragma unroll
        for (int nf = 0; nf < 4; nf++) {
#pragma unroll
            for (int i = 0; i < 4; i++) {
                int m   = m0 + mf * 16 + gid + (i >> 1) * 8;
                int c   = nf * 8 + tig * 2 + (i & 1);     // channel 0..31
                int pix = ytile * 256 + m;

                float yg1 = acc[0][mf][nf][i] + sBias[c];
                float yg2 = acc[1][mf][nf][i] + sBias[32 + c];
                float yz  = acc[2][mf][nf][i] + sBias[64 + c];

                size_t xbase = (((size_t)(t * 8 + b)) * 128 + c) * HW + pix;
                float a1 = g_XC[xbase]           + yg1;
                float a2 = g_XC[xbase + 32 * HW] + yg2;
                float az = g_XC[xbase + 64 * HW] + yz;

                size_t off = ((size_t)b * 32 + c) * HW + pix;
                float ms1 = fsigmoid(a1);
                float zv  = g_Z[off];
                float zn  = fmaf(ms1, ftanh(az) - zv, zv);
                g_Z[off]  = zn;
                g_G2[off] = fsigmoid(a2);
            }
        }
    }
}

__global__ void init_k()
{
    int idx = blockIdx.x * blockDim.x + threadIdx.x;
    if (idx < 8 * 32 * 4096) { g_Y[idx] = 0.0f; g_Z[idx] = 0.0f; }
}

extern "C" void kernel_launch(void* const* d_in, const int* in_sizes, int n_in,
                              void* d_out, int out_size)
{
    const float* X  = (const float*)d_in[0];
    const float* Wx = (const float*)d_in[1];
    const float* bx = (const float*)d_in[2];
    const float* Wy = (const float*)d_in[3];
    const float* by = (const float*)d_in[4];
    const float* Wz = (const float*)d_in[5];
    const float* bz = (const float*)d_in[6];
    float* out = (float*)d_out;

    static bool attr_done = false;
    if (!attr_done) {
        cudaFuncSetAttribute(conv_tc<0>, cudaFuncAttributeMaxDynamicSharedMemorySize, SMEM_SZ);
        cudaFuncSetAttribute(conv_tc<2>, cudaFuncAttributeMaxDynamicSharedMemorySize, SMEM_SZ);
        cudaFuncSetAttribute(convY_k,    cudaFuncAttributeMaxDynamicSharedMemorySize, YSMEM_SZ);
        attr_done = true;
    }

    u16* WH = nullptr; u16* WL = nullptr;
    cudaGetSymbolAddress((void**)&WH, g_WH);
    cudaGetSymbolAddress((void**)&WL, g_WL);

    // One-time-per-replay prep (deterministic): weights -> bf16 hi/lo.
    prep_w<<<(256 * KPAD + 255) / 256, 256>>>(Wx, Wy, Wz);

    // Reset recurrent state.
    init_k<<<(8 * 32 * 4096 + 255) / 256, 256>>>();

    // Precompute all input convolutions (tensor cores).
    conv_tc<0><<<dim3(16, 4, 400), 256, SMEM_SZ>>>(X, WH, WL, bx, nullptr, 0);

    // Recurrence: 50 steps, 2 launches each.
    const u16* WzH = WH + (size_t)224 * KPAD;
    const u16* WzL = WL + (size_t)224 * KPAD;
    for (int t = 0; t < Tn; t++) {
        convY_k<<<dim3(16, 8), 256, YSMEM_SZ>>>(by, t);
        conv_tc<2><<<dim3(16, 1, 8), 256, SMEM_SZ>>>(nullptr, WzH, WzL, bz, out, t);
    }
}

// round 13
// speedup vs baseline: 1.0085x; 1.0085x over previous
#include <cuda_runtime.h>
#include <cuda_bf16.h>
#include <cstdint>
#include <math.h>

#define HW 4096
#define Tn 50

typedef uint32_t u32;
typedef unsigned short u16;

// Scratch (static __device__ arrays — allocation-free per harness rules)
__device__ float g_XC[400u * 128u * 4096u];   // [t*8+b][128][4096]
__device__ float g_Y[8 * 32 * 4096];
__device__ float g_Z[8 * 32 * 4096];
__device__ float g_G2[8 * 32 * 4096];

#define KPAD   296            // u16 elements per weight row (288 used)
#define KPAD32 (KPAD / 2)     // 148 u32 per row
// Packed bf16 hi/lo weights: rows 0..127 = Wx, 128..223 = Wy, 224..255 = Wz
__device__ u16 g_WH[256 * KPAD];
__device__ u16 g_WL[256 * KPAD];

__device__ __forceinline__ float fsigmoid(float x) {
    return 1.0f / (1.0f + __expf(-x));
}
__device__ __forceinline__ float ftanh(float x) {
    x = fminf(fmaxf(x, -12.0f), 12.0f);
    float e = __expf(2.0f * x);
    return 1.0f - 2.0f / (e + 1.0f);
}

// mma.sync m16n8k16 bf16 (baseline PTX, sm_80+; tensor pipe)
__device__ __forceinline__ void mma16816(float* d,
                                         u32 a0, u32 a1, u32 a2, u32 a3,
                                         u32 b0, u32 b1) {
    asm volatile(
        "mma.sync.aligned.m16n8k16.row.col.f32.bf16.bf16.f32 "
        "{%0,%1,%2,%3}, {%4,%5,%6,%7}, {%8,%9}, {%0,%1,%2,%3};"
        : "+f"(d[0]), "+f"(d[1]), "+f"(d[2]), "+f"(d[3])
        : "r"(a0), "r"(a1), "r"(a2), "r"(a3), "r"(b0), "r"(b1));
}

// ---------------------------------------------------------------------------
// One-time weight prep: float -> bf16 hi/lo, layout [row][k], k = tap*32 + ci
// ---------------------------------------------------------------------------
__global__ void prep_w(const float* __restrict__ Wx,
                       const float* __restrict__ Wy,
                       const float* __restrict__ Wz)
{
    int idx = blockIdx.x * 256 + threadIdx.x;
    if (idx >= 256 * KPAD) return;
    int row = idx / KPAD, k = idx - row * KPAD;
    u16 h = 0, l = 0;
    if (k < 288) {
        int tap = k >> 5, ci = k & 31;
        const float* W; int co;
        if (row < 128)      { W = Wx; co = row; }
        else if (row < 224) { W = Wy; co = row - 128; }
        else                { W = Wz; co = row - 224; }
        float w = W[((size_t)co * 32 + ci) * 9 + tap];
        __nv_bfloat16 wh = __float2bfloat16(w);
        __nv_bfloat16 wl = __float2bfloat16(w - __bfloat162float(wh));
        h = __bfloat16_as_ushort(wh);
        l = __bfloat16_as_ushort(wl);
    }
    g_WH[idx] = h;
    g_WL[idx] = l;
}

// ---------------------------------------------------------------------------
// Shared-memory layout for conv_tc (32 co per CTA) — unchanged from R11
// ---------------------------------------------------------------------------
#define CIPAD   40
#define AELEMS  (6 * 66 * CIPAD)                 // 15840
#define OFF_AH  0
#define OFF_AL  (AELEMS * 2)                     // 31680
#define OFF_WH  (OFF_AL + AELEMS * 2)            // 63360
#define OFF_WL  (OFF_WH + 32 * KPAD * 2)         // +18944
#define OFF_BI  (OFF_WL + 32 * KPAD * 2)
#define SMEM_SZ (OFF_BI + 128)

// ---------------------------------------------------------------------------
// conv_tc: 3x3 SAME conv, Cin=32, 32 co per CTA (used for MODE0 and MODE2).
// MODE 0: X -> g_XC (grid = 16 x 4 x 400)
// MODE 2: g_Z -> fused Y update -> g_Y and out (grid = 16 x 1 x 8)
// ---------------------------------------------------------------------------
template<int MODE>
__global__ void __launch_bounds__(256, 2)
conv_tc(const float* __restrict__ X,
        const u16* __restrict__ gWh,   // pre-sliced for this conv
        const u16* __restrict__ gWl,
        const float* __restrict__ bias,
        float* __restrict__ out,
        int t)
{
    extern __shared__ char smem[];
    u16*   sAh   = (u16*)(smem + OFF_AH);
    u16*   sAl   = (u16*)(smem + OFF_AL);
    u16*   sWh   = (u16*)(smem + OFF_WH);
    u16*   sWl   = (u16*)(smem + OFF_WL);
    float* sBias = (float*)(smem + OFF_BI);

    const int tid   = threadIdx.x;
    const int ytile = blockIdx.x;        // 4 image rows each
    const int cog   = blockIdx.y;
    const int img   = blockIdx.z;

    int b, ti;
    if (MODE == 0) { b = img & 7; ti = img >> 3; }
    else           { b = img;     ti = t; }

    const float* src;
    size_t in_base; int chstride;
    if (MODE == 0) { src = X;   in_base = ((size_t)b * 32 * Tn + ti) * HW; chstride = Tn * HW; }
    else           { src = g_Z; in_base = (size_t)b * 32 * HW; chstride = HW; }

    const int y0 = ytile * 4;

    // ---- stage weights: straight u32 copy from prepped arrays ----
    {
        const u32* wh32 = (const u32*)gWh + (size_t)cog * 32 * KPAD32;
        const u32* wl32 = (const u32*)gWl + (size_t)cog * 32 * KPAD32;
        for (int e = tid; e < 32 * KPAD32; e += 256) {
            ((u32*)sWh)[e] = wh32[e];
            ((u32*)sWl)[e] = wl32[e];
        }
    }
    if (tid < 32) sBias[tid] = bias[cog * 32 + tid];

    // ---- stage halo tile [6][66][ci] channel-major, SAME zero-padding ----
    for (int e = tid; e < 32 * 6 * 66; e += 256) {
        int ci = e / 396, r = e - ci * 396;
        int hy = r / 66,  hx = r - hy * 66;
        int gy = y0 - 1 + hy, gx = hx - 1;
        float v = 0.0f;
        if ((unsigned)gy < 64u && (unsigned)gx < 64u)
            v = src[in_base + (size_t)ci * chstride + gy * 64 + gx];
        __nv_bfloat16 h = __float2bfloat16(v);
        __nv_bfloat16 l = __float2bfloat16(v - __bfloat162float(h));
        int slot = (hy * 66 + hx) * CIPAD + ci;
        sAh[slot] = __bfloat16_as_ushort(h);
        sAl[slot] = __bfloat16_as_ushort(l);
    }
    __syncthreads();

    // ---- warp GEMM: M=32, N=32 ----
    const int wid  = tid >> 5;
    const int lane = tid & 31;
    const int gid  = lane >> 2;
    const int tig  = lane & 3;
    const int m0   = wid * 32;

    int abase[4];
#pragma unroll
    for (int r = 0; r < 4; r++) {
        int m  = m0 + r * 8 + gid;
        int py = m >> 6, px = m & 63;
        abase[r] = (py * 66 + px) * CIPAD + tig * 2;
    }
    int bbase[4];
#pragma unroll
    for (int nf = 0; nf < 4; nf++)
        bbase[nf] = (nf * 8 + gid) * KPAD + tig * 2;

    float acc[2][4][4];
#pragma unroll
    for (int mf = 0; mf < 2; mf++)
#pragma unroll
        for (int nf = 0; nf < 4; nf++)
#pragma unroll
            for (int i = 0; i < 4; i++) acc[mf][nf][i] = 0.0f;

#pragma unroll 1
    for (int tap = 0; tap < 9; tap++) {
        const int dy = tap / 3, dx = tap - dy * 3;
        const int aofs_t = (dy * 66 + dx) * CIPAD;
        const int bofs_t = tap * 32;
#pragma unroll
        for (int kc = 0; kc < 2; kc++) {
            const int aofs = aofs_t + kc * 16;
            const int bofs = bofs_t + kc * 16;

            u32 Ah[2][4], Al[2][4];
#pragma unroll
            for (int mf = 0; mf < 2; mf++) {
                int i0 = abase[2 * mf]     + aofs;
                int i1 = abase[2 * mf + 1] + aofs;
                Ah[mf][0] = *(const u32*)&sAh[i0];
                Ah[mf][1] = *(const u32*)&sAh[i1];
                Ah[mf][2] = *(const u32*)&sAh[i0 + 8];
                Ah[mf][3] = *(const u32*)&sAh[i1 + 8];
                Al[mf][0] = *(const u32*)&sAl[i0];
                Al[mf][1] = *(const u32*)&sAl[i1];
                Al[mf][2] = *(const u32*)&sAl[i0 + 8];
                Al[mf][3] = *(const u32*)&sAl[i1 + 8];
            }
#pragma unroll
            for (int nf = 0; nf < 4; nf++) {
                int j = bbase[nf] + bofs;
                u32 Bh0 = *(const u32*)&sWh[j];
                u32 Bh1 = *(const u32*)&sWh[j + 8];
                u32 Bl0 = *(const u32*)&sWl[j];
                u32 Bl1 = *(const u32*)&sWl[j + 8];
#pragma unroll
                for (int mf = 0; mf < 2; mf++) {
                    mma16816(acc[mf][nf], Ah[mf][0], Ah[mf][1], Ah[mf][2], Ah[mf][3], Bh0, Bh1);
                    mma16816(acc[mf][nf], Al[mf][0], Al[mf][1], Al[mf][2], Al[mf][3], Bh0, Bh1);
                    mma16816(acc[mf][nf], Ah[mf][0], Ah[mf][1], Ah[mf][2], Ah[mf][3], Bl0, Bl1);
                }
            }
        }
    }

    // ---- epilogue ----
#pragma unroll
    for (int mf = 0; mf < 2; mf++) {
#pragma unroll
        for (int nf = 0; nf < 4; nf++) {
#pragma unroll
            for (int i = 0; i < 4; i++) {
                int m   = m0 + mf * 16 + gid + (i >> 1) * 8;
                int n   = nf * 8 + tig * 2 + (i & 1);
                int pix = ytile * 256 + m;
                int co  = cog * 32 + n;
                float v = acc[mf][nf][i] + sBias[n];
                if (MODE == 0) {
                    g_XC[((size_t)img * 128 + co) * HW + pix] = v;
                } else {
                    size_t off = ((size_t)b * 32 + co) * HW + pix;
                    float g2 = g_G2[off];
                    float xy = g_XC[(((size_t)(t * 8 + b)) * 128 + 96 + co) * HW + pix];
                    float yv = g_Y[off];
                    float yn = fmaf(g2, ftanh(xy + v) - yv, yv);
                    g_Y[off] = yn;
                    out[((size_t)(b * 32 + co) * Tn + t) * HW + pix] = yn;
                }
            }
        }
    }
}

// ---------------------------------------------------------------------------
// Fused conv(Y, Wy) + gates + Z update.
// 256 thr = 8 warps; warp w owns M rows [w*32, w*32+32) and ALL 96 channels
// (nj = 0:yg1, 1:yg2, 2:yz). Each thread's acc triplet across nj shares the
// same (pixel, channel) -> Z/G2 update fully thread-local. No g_yconv.
// grid = (16 ytiles, 8 batch)
// ---------------------------------------------------------------------------
#define YOFF_WH  (AELEMS * 4)                    // after sAh+sAl (63360)
#define YOFF_WL  (YOFF_WH + 96 * KPAD * 2)       // +56832
#define YOFF_BI  (YOFF_WL + 96 * KPAD * 2)
#define YSMEM_SZ (YOFF_BI + 512)                 // ~177.5 KB

__global__ void __launch_bounds__(256, 1)
convY_k(const float* __restrict__ by, int t)
{
    extern __shared__ char smem[];
    u16*   sAh   = (u16*)(smem);
    u16*   sAl   = (u16*)(smem + AELEMS * 2);
    u16*   sWh   = (u16*)(smem + YOFF_WH);
    u16*   sWl   = (u16*)(smem + YOFF_WL);
    float* sBias = (float*)(smem + YOFF_BI);

    const int tid   = threadIdx.x;
    const int ytile = blockIdx.x;
    const int b     = blockIdx.y;
    const int y0    = ytile * 4;

    // ---- stage weights (Wy rows = 128..223 of prepped arrays) ----
    {
        const u32* wh32 = (const u32*)g_WH + (size_t)128 * KPAD32;
        const u32* wl32 = (const u32*)g_WL + (size_t)128 * KPAD32;
        for (int e = tid; e < 96 * KPAD32; e += 256) {
            ((u32*)sWh)[e] = wh32[e];
            ((u32*)sWl)[e] = wl32[e];
        }
    }
    if (tid < 96) sBias[tid] = by[tid];

    // ---- stage halo from g_Y ----
    const size_t in_base = (size_t)b * 32 * HW;
    for (int e = tid; e < 32 * 6 * 66; e += 256) {
        int ci = e / 396, r = e - ci * 396;
        int hy = r / 66,  hx = r - hy * 66;
        int gy = y0 - 1 + hy, gx = hx - 1;
        float v = 0.0f;
        if ((unsigned)gy < 64u && (unsigned)gx < 64u)
            v = g_Y[in_base + (size_t)ci * HW + gy * 64 + gx];
        __nv_bfloat16 h = __float2bfloat16(v);
        __nv_bfloat16 l = __float2bfloat16(v - __bfloat162float(h));
        int slot = (hy * 66 + hx) * CIPAD + ci;
        sAh[slot] = __bfloat16_as_ushort(h);
        sAl[slot] = __bfloat16_as_ushort(l);
    }
    __syncthreads();

    const int wid  = tid >> 5;
    const int lane = tid & 31;
    const int gid  = lane >> 2;
    const int tig  = lane & 3;
    const int m0   = wid * 32;

    int abase[4];
#pragma unroll
    for (int r = 0; r < 4; r++) {
        int m  = m0 + r * 8 + gid;
        int py = m >> 6, px = m & 63;
        abase[r] = (py * 66 + px) * CIPAD + tig * 2;
    }

    float acc[3][2][4][4];
#pragma unroll
    for (int nj = 0; nj < 3; nj++)
#pragma unroll
        for (int mf = 0; mf < 2; mf++)
#pragma unroll
            for (int nf = 0; nf < 4; nf++)
#pragma unroll
                for (int i = 0; i < 4; i++) acc[nj][mf][nf][i] = 0.0f;

#pragma unroll 1
    for (int tap = 0; tap < 9; tap++) {
        const int dy = tap / 3, dx = tap - dy * 3;
        const int aofs_t = (dy * 66 + dx) * CIPAD;
        const int bofs_t = tap * 32;
#pragma unroll
        for (int kc = 0; kc < 2; kc++) {
            const int aofs = aofs_t + kc * 16;
            const int bofs = bofs_t + kc * 16;

            u32 Ah[2][4], Al[2][4];
#pragma unroll
            for (int mf = 0; mf < 2; mf++) {
                int i0 = abase[2 * mf]     + aofs;
                int i1 = abase[2 * mf + 1] + aofs;
                Ah[mf][0] = *(const u32*)&sAh[i0];
                Ah[mf][1] = *(const u32*)&sAh[i1];
                Ah[mf][2] = *(const u32*)&sAh[i0 + 8];
                Ah[mf][3] = *(const u32*)&sAh[i1 + 8];
                Al[mf][0] = *(const u32*)&sAl[i0];
                Al[mf][1] = *(const u32*)&sAl[i1];
                Al[mf][2] = *(const u32*)&sAl[i0 + 8];
                Al[mf][3] = *(const u32*)&sAl[i1 + 8];
            }
#pragma unroll
            for (int nj = 0; nj < 3; nj++) {
#pragma unroll
                for (int nf = 0; nf < 4; nf++) {
                    int j = (nj * 32 + nf * 8 + gid) * KPAD + tig * 2 + bofs;
                    u32 Bh0 = *(const u32*)&sWh[j];
                    u32 Bh1 = *(const u32*)&sWh[j + 8];
                    u32 Bl0 = *(const u32*)&sWl[j];
                    u32 Bl1 = *(const u32*)&sWl[j + 8];
#pragma unroll
                    for (int mf = 0; mf < 2; mf++) {
                        mma16816(acc[nj][mf][nf], Ah[mf][0], Ah[mf][1], Ah[mf][2], Ah[mf][3], Bh0, Bh1);
                        mma16816(acc[nj][mf][nf], Al[mf][0], Al[mf][1], Al[mf][2], Al[mf][3], Bh0, Bh1);
                        mma16816(acc[nj][mf][nf], Ah[mf][0], Ah[mf][1], Ah[mf][2], Ah[mf][3], Bl0, Bl1);
                    }
                }
            }
        }
    }

    // ---- fused gate/Z epilogue: all data thread-local ----
#pragma unroll
    for (int mf = 0; mf < 2; mf++) {
#pragma unroll
        for (int nf = 0; nf < 4; nf++) {
#pragma unroll
            for (int i = 0; i < 4; i++) {
                int m   = m0 + mf * 16 + gid + (i >> 1) * 8;
                int c   = nf * 8 + tig * 2 + (i & 1);     // channel 0..31
                int pix = ytile * 256 + m;

                float yg1 = acc[0][mf][nf][i] + sBias[c];
                float yg2 = acc[1][mf][nf][i] + sBias[32 + c];
                float yz  = acc[2][mf][nf][i] + sBias[64 + c];

                size_t xbase = (((size_t)(t * 8 + b)) * 128 + c) * HW + pix;
                float a1 = g_XC[xbase]           + yg1;
                float a2 = g_XC[xbase + 32 * HW] + yg2;
                float az = g_XC[xbase + 64 * HW] + yz;

                size_t off = ((size_t)b * 32 + c) * HW + pix;
                float ms1 = fsigmoid(a1);
                float zv  = g_Z[off];
                float zn  = fmaf(ms1, ftanh(az) - zv, zv);
                g_Z[off]  = zn;
                g_G2[off] = fsigmoid(a2);
            }
        }
    }
}

__global__ void init_k()
{
    int idx = blockIdx.x * blockDim.x + threadIdx.x;
    if (idx < 8 * 32 * 4096) { g_Y[idx] = 0.0f; g_Z[idx] = 0.0f; }
}

extern "C" void kernel_launch(void* const* d_in, const int* in_sizes, int n_in,
                              void* d_out, int out_size)
{
    const float* X  = (const float*)d_in[0];
    const float* Wx = (const float*)d_in[1];
    const float* bx = (const float*)d_in[2];
    const float* Wy = (const float*)d_in[3];
    const float* by = (const float*)d_in[4];
    const float* Wz = (const float*)d_in[5];
    const float* bz = (const float*)d_in[6];
    float* out = (float*)d_out;

    static bool attr_done = false;
    if (!attr_done) {
        cudaFuncSetAttribute(conv_tc<0>, cudaFuncAttributeMaxDynamicSharedMemorySize, SMEM_SZ);
        cudaFuncSetAttribute(conv_tc<2>, cudaFuncAttributeMaxDynamicSharedMemorySize, SMEM_SZ);
        cudaFuncSetAttribute(convY_k,    cudaFuncAttributeMaxDynamicSharedMemorySize, YSMEM_SZ);
        attr_done = true;
    }

    u16* WH = nullptr; u16* WL = nullptr;
    cudaGetSymbolAddress((void**)&WH, g_WH);
    cudaGetSymbolAddress((void**)&WL, g_WL);

    // One-time-per-replay prep (deterministic): weights -> bf16 hi/lo.
    prep_w<<<(256 * KPAD + 255) / 256, 256>>>(Wx, Wy, Wz);

    // Reset recurrent state.
    init_k<<<(8 * 32 * 4096 + 255) / 256, 256>>>();

    // Precompute all input convolutions (tensor cores).
    conv_tc<0><<<dim3(16, 4, 400), 256, SMEM_SZ>>>(X, WH, WL, bx, nullptr, 0);

    // Recurrence: 50 steps, 2 launches each.
    const u16* WzH = WH + (size_t)224 * KPAD;
    const u16* WzL = WL + (size_t)224 * KPAD;
    for (int t = 0; t < Tn; t++) {
        convY_k<<<dim3(16, 8), 256, YSMEM_SZ>>>(by, t);
        conv_tc<2><<<dim3(16, 1, 8), 256, SMEM_SZ>>>(nullptr, WzH, WzL, bz, out, t);
    }
}